// round 13
// baseline (speedup 1.0000x reference)
#include <cuda_runtime.h>
#include <cuda_bf16.h>
#include <cstdint>

// ---------------------------------------------------------------------------
// Gaussian rasterizer, R13: ONE kernel launch.
//  - CTAs 0-1 project all 512 gaussians (1/thread) into device globals,
//    threadfence, then release a done-flag.
//  - All CTAs (thread 0) spin on the flag, __syncthreads, then run the R12
//    raster: LDG.128 cull word, rank-sort survivors, vsub2 mask, batch-4
//    EX2 composite with early-out.
//  - Replay-safe: last of 256 CTAs resets the flag/counters to 0.
// ---------------------------------------------------------------------------

#define NG    512
#define IMG   256
#define TW    16
#define TH    16
#define NT    256
#define NWARP (NT/32)
#define NCTA  ((IMG/TW)*(IMG/TH))   // 256

__device__ float4 g_rec[NG][3];
__device__ uint4  g_cull[NG];
__device__ int    g_done = 0;
__device__ int    g_fin  = 0;

__device__ __forceinline__ float ex2(float x) {
    float y;
    asm("ex2.approx.ftz.f32 %0, %1;" : "=f"(y) : "f"(x));
    return y;
}

__global__ __launch_bounds__(NT)
void gs_fused(const float* __restrict__ pos,
              const float* __restrict__ cov3d,
              const float* __restrict__ opac,
              const float* __restrict__ cols,
              const float* __restrict__ Km,
              const float* __restrict__ Rm,
              const float* __restrict__ tv,
              float* __restrict__ out)
{
    __shared__ float4             rec[NG + 4][3];  // ~24.2 KB
    __shared__ unsigned long long skey[NG];        // 4 KB
    __shared__ int                warpTotals[NWARP];

    const int tid = threadIdx.x;
    const int bid = blockIdx.y * (IMG/TW) + blockIdx.x;

    // ================= producer phase: CTAs 0,1 project =================
    if (bid < 2) {
        const int g = bid * NT + tid;

        const float r00 = Rm[0], r01 = Rm[1], r02 = Rm[2];
        const float r10 = Rm[3], r11 = Rm[4], r12 = Rm[5];
        const float r20 = Rm[6], r21 = Rm[7], r22 = Rm[8];
        const float fx  = Km[0], fy = Km[4];

        const float p0 = pos[3*g+0], p1 = pos[3*g+1], p2 = pos[3*g+2];

        const float cam0 = r00*p0 + r01*p1 + r02*p2 + tv[0];
        const float cam1 = r10*p0 + r11*p1 + r12*p2 + tv[1];
        const float cam2 = r20*p0 + r21*p1 + r22*p2 + tv[2];

        const float pr0 = Km[0]*cam0 + Km[1]*cam1 + Km[2]*cam2;
        const float pr1 = Km[3]*cam0 + Km[4]*cam1 + Km[5]*cam2;
        const float pr2 = Km[6]*cam0 + Km[7]*cam1 + Km[8]*cam2;
        const float rz = 1.0f / pr2;
        const float mx = pr0 * rz;
        const float my = pr1 * rz;

        const float z   = cam2;
        const float iz  = 1.0f / z;
        const float jx0 = fx * iz;
        const float jx2 = -fx * cam0 * iz * iz;
        const float jy1 = fy * iz;
        const float jy2 = -fy * cam1 * iz * iz;

        const float P00 = jx0*r00 + jx2*r20;
        const float P01 = jx0*r01 + jx2*r21;
        const float P02 = jx0*r02 + jx2*r22;
        const float P10 = jy1*r10 + jy2*r20;
        const float P11 = jy1*r11 + jy2*r21;
        const float P12 = jy1*r12 + jy2*r22;

        const float c00 = cov3d[9*g+0];
        const float c01 = cov3d[9*g+1];
        const float c02 = cov3d[9*g+2];
        const float c11 = cov3d[9*g+4];
        const float c12 = cov3d[9*g+5];
        const float c22 = cov3d[9*g+8];

        const float t00 = c00*P00 + c01*P01 + c02*P02;
        const float t01 = c01*P00 + c11*P01 + c12*P02;
        const float t02 = c02*P00 + c12*P01 + c22*P02;
        const float t10 = c00*P10 + c01*P11 + c02*P12;
        const float t11 = c01*P10 + c11*P11 + c12*P12;
        const float t12 = c02*P10 + c12*P11 + c22*P12;

        const float a = P00*t00 + P01*t01 + P02*t02 + 0.3f;
        const float b = P10*t00 + P11*t01 + P12*t02;
        const float c = P10*t10 + P11*t11 + P12*t12 + 0.3f;

        const float det  = fmaxf(a*c - b*b, 1e-8f);
        const float idet = 1.0f / det;
        const float e00 = -0.72134752f * c * idet;
        const float e01 =  1.44269504f * b * idet;
        const float e11 = -0.72134752f * a * idet;

        const float hd = (a - c) * 0.5f;
        const float max_eig = (a + c)*0.5f + sqrtf(fmaxf(hd*hd + b*b, 1e-8f));
        const float radius = 3.0f * sqrtf(max_eig);

        const float x_min = fmaxf(0.0f,       truncf(mx - radius));
        const float x_max = fminf((float)IMG, truncf(mx + radius) + 1.0f);
        const float y_min = fmaxf(0.0f,       truncf(my - radius));
        const float y_max = fminf((float)IMG, truncf(my + radius) + 1.0f);

        const float bias = __log2f(opac[g]);

        unsigned lo, hm1;
        if (x_max <= x_min || y_max <= y_min) {
            lo  = 0x7FFF7FFFu;
            hm1 = 0u;
        } else {
            const unsigned x0  = (unsigned)x_min;
            const unsigned y0  = (unsigned)y_min;
            const unsigned x1m = (unsigned)(x_max - 1.0f);
            const unsigned y1m = (unsigned)(y_max - 1.0f);
            lo  = x0  | (y0  << 16);
            hm1 = x1m | (y1m << 16);
        }

        g_rec[g][0] = make_float4(mx, my, e00, e01);
        g_rec[g][1] = make_float4(e11, bias,
                                  __uint_as_float(lo), __uint_as_float(hm1));
        g_rec[g][2] = make_float4(cols[3*g+0], cols[3*g+1], cols[3*g+2], 0.f);
        g_cull[g] = make_uint4(lo, hm1, __float_as_uint(z), 0u);

        __threadfence();
        __syncthreads();
        if (tid == 0) atomicAdd(&g_done, 1);
    }

    // ================= handoff: wait for both producer CTAs =============
    if (tid == 0) {
        while (*(volatile int*)&g_done != 2) { }
    }
    __syncthreads();
    __threadfence();   // acquire: order g_rec/g_cull reads after flag

    const int lane = tid & 31;
    const int wid  = tid >> 5;
    const int tileX = blockIdx.x * TW;
    const int tileY = blockIdx.y * TH;

    // ---------------- phase 1: cull 2 gaussians/thread ----------------
    bool  flg[2];
    unsigned long long key[2];
    float4 R0[2], R1[2], R2[2];

    #pragma unroll
    for (int s = 0; s < 2; s++) {
        const int g = tid + s * NT;
        const uint4 cw = g_cull[g];                     // coalesced LDG.128
        const int x0  = (int)(cw.x & 0xffffu), y0  = (int)(cw.x >> 16);
        const int x1m = (int)(cw.y & 0xffffu), y1m = (int)(cw.y >> 16);
        flg[s] = (x0 < tileX + TW) & (x1m >= tileX) &
                 (y0 < tileY + TH) & (y1m >= tileY);
        key[s] = ((unsigned long long)cw.z << 16) | (unsigned long long)g;
        if (flg[s]) {                                   // L2 fetch, overlaps rank
            R0[s] = g_rec[g][0];
            R1[s] = g_rec[g][1];
            R2[s] = g_rec[g][2];
        }
    }

    // ---------------- phase 2: compaction slots ----------------
    const unsigned m0 = __ballot_sync(0xffffffffu, flg[0]);
    const unsigned m1 = __ballot_sync(0xffffffffu, flg[1]);
    if (lane == 0) warpTotals[wid] = __popc(m0) | (__popc(m1) << 16);
    __syncthreads();

    int prefix = 0, total = 0;
    #pragma unroll
    for (int w = 0; w < NWARP; w++) {
        const int t = warpTotals[w];
        if (w < wid) prefix += t;
        total += t;
    }
    const int count0 = total & 0xffff;
    const int count  = count0 + (total >> 16);
    const unsigned lm = (1u << lane) - 1u;
    const int pos0 = (prefix & 0xffff) + __popc(m0 & lm);
    const int pos1 = count0 + (prefix >> 16) + __popc(m1 & lm);

    if (flg[0]) skey[pos0] = key[0];
    if (flg[1]) skey[pos1] = key[1];
    __syncthreads();

    // ---------------- phase 3: rank over survivors only ----------------
    int rank0 = 0, rank1 = 0;
    if (flg[0] | flg[1]) {
        for (int j = 0; j < count; j++) {
            const unsigned long long kj = skey[j];
            rank0 += (kj < key[0]);
            rank1 += (kj < key[1]);
        }
    }
    if (flg[0]) { rec[rank0][0] = R0[0]; rec[rank0][1] = R1[0]; rec[rank0][2] = R2[0]; }
    if (flg[1]) { rec[rank1][0] = R0[1]; rec[rank1][1] = R1[1]; rec[rank1][2] = R2[1]; }

    const int countPad = (count + 3) & ~3;
    for (int t2 = count + tid; t2 < countPad; t2 += NT) {
        rec[t2][0] = make_float4(0.f, 0.f, 0.f, 0.f);
        rec[t2][1] = make_float4(0.f, 0.f,
                                 __uint_as_float(0x7FFF7FFFu), 0.f);
        rec[t2][2] = make_float4(0.f, 0.f, 0.f, 0.f);
    }
    __syncthreads();

    // ---------------- phase 4: composite, 1 px/thread ----------------
    const int pxi = tileX + (tid & (TW - 1));
    const int pyi = tileY + (tid >> 4);
    const float pxf = (float)pxi;
    const float pyf = (float)pyi;
    const unsigned pxy = (unsigned)pxi | ((unsigned)pyi << 16);

    float T = 1.0f, rr = 0.0f, gg = 0.0f, bb = 0.0f;
    for (int base = 0; base < countPad; base += 4) {
        float4 q0[4], q1[4], q2[4];
        #pragma unroll
        for (int i = 0; i < 4; i++) {
            q0[i] = rec[base+i][0];
            q1[i] = rec[base+i][1];
            q2[i] = rec[base+i][2];
        }
        float gs[4];
        #pragma unroll
        for (int i = 0; i < 4; i++) {
            const unsigned lo  = __float_as_uint(q1[i].z);
            const unsigned hm1 = __float_as_uint(q1[i].w);
            const unsigned ua  = __vsub2(pxy, lo);
            const unsigned ub  = __vsub2(hm1, pxy);
            const bool inb = ((ua | ub) & 0x80008000u) == 0u;

            const float dx = pxf - q0[i].x;
            const float dy = pyf - q0[i].y;
            const float u  = fmaf(q1[i].x * dy, dy, q1[i].y);   // e11*dy^2 + bias
            const float pl = fmaf(q0[i].w, dy, q0[i].z * dx);   // e01*dy + e00*dx
            const float e  = fmaf(pl, dx, u);
            gs[i] = inb ? ex2(e) : 0.0f;                        // alpha
        }
        #pragma unroll
        for (int i = 0; i < 4; i++) {
            const float tg = T * gs[i];
            rr = fmaf(tg, q2[i].x, rr);
            gg = fmaf(tg, q2[i].y, gg);
            bb = fmaf(tg, q2[i].z, bb);
            T  = T - tg;
        }
        if (T < 1e-5f) break;
    }

    const int idx = (pyi * IMG + pxi) * 3;
    out[idx + 0] = rr;
    out[idx + 1] = gg;
    out[idx + 2] = bb;

    // ================= replay-safe reset =================
    __syncthreads();
    if (tid == 0) {
        const int r = atomicAdd(&g_fin, 1);
        if (r == NCTA - 1) {         // last CTA: everyone is past the spin
            atomicExch(&g_done, 0);
            atomicExch(&g_fin, 0);
        }
    }
}

extern "C" void kernel_launch(void* const* d_in, const int* in_sizes, int n_in,
                              void* d_out, int out_size)
{
    const float* pos   = (const float*)d_in[0];  // (512,3)
    const float* cov3d = (const float*)d_in[1];  // (512,3,3)
    const float* opac  = (const float*)d_in[2];  // (512,1)
    const float* cols  = (const float*)d_in[3];  // (512,3)
    const float* Km    = (const float*)d_in[4];  // (3,3)
    const float* Rm    = (const float*)d_in[5];  // (3,3)
    const float* tv    = (const float*)d_in[6];  // (3,)
    float* out = (float*)d_out;                  // (256,256,3)

    gs_fused<<<dim3(IMG/TW, IMG/TH), NT>>>(pos, cov3d, opac, cols, Km, Rm, tv, out);
}

// round 14
// speedup vs baseline: 1.2119x; 1.2119x over previous
#include <cuda_runtime.h>
#include <cuda_bf16.h>
#include <cstdint>

// ---------------------------------------------------------------------------
// Fused Gaussian rasterizer, R14 = R6 single-launch structure plus:
//  - vsub2 SIMD u16 in-box mask (canonicalized empty boxes)
//  - slot-parallel rank: only ceil(count/32) warps pay the O(count) loop
// 256 CTAs x 256 threads, 16x16 tiles, 2 gaussians/thread register projection.
// ---------------------------------------------------------------------------

#define NG    512
#define IMG   256
#define TW    16
#define TH    16
#define NT    256
#define NWARP (NT/32)

__device__ __forceinline__ float ex2(float x) {
    float y;
    asm("ex2.approx.ftz.f32 %0, %1;" : "=f"(y) : "f"(x));
    return y;
}

__global__ __launch_bounds__(NT)
void gs_fused(const float* __restrict__ pos,
              const float* __restrict__ cov3d,
              const float* __restrict__ opac,
              const float* __restrict__ cols,
              const float* __restrict__ Km,
              const float* __restrict__ Rm,
              const float* __restrict__ tv,
              float* __restrict__ out)
{
    __shared__ float4             rec[NG + 4][3];  // ~24.2 KB
    __shared__ unsigned long long skey[NG];        // 4 KB
    __shared__ short              srank[NG];       // 1 KB
    __shared__ int                warpTotals[NWARP];

    const int tid  = threadIdx.x;
    const int lane = tid & 31;
    const int wid  = tid >> 5;

    const int tileX = blockIdx.x * TW;
    const int tileY = blockIdx.y * TH;

    const float r00 = Rm[0], r01 = Rm[1], r02 = Rm[2];
    const float r10 = Rm[3], r11 = Rm[4], r12 = Rm[5];
    const float r20 = Rm[6], r21 = Rm[7], r22 = Rm[8];
    const float fx  = Km[0], fy = Km[4];

    // ---------------- phase 1: project 2 gaussians/thread ----------------
    bool  flg[2];
    unsigned long long key[2];
    float4 R0v[2], R1v[2], R2v[2];

    #pragma unroll
    for (int s = 0; s < 2; s++) {
        const int g = tid + s * NT;
        const float p0 = pos[3*g+0], p1 = pos[3*g+1], p2 = pos[3*g+2];

        const float cam0 = r00*p0 + r01*p1 + r02*p2 + tv[0];
        const float cam1 = r10*p0 + r11*p1 + r12*p2 + tv[1];
        const float cam2 = r20*p0 + r21*p1 + r22*p2 + tv[2];

        const float pr0 = Km[0]*cam0 + Km[1]*cam1 + Km[2]*cam2;
        const float pr1 = Km[3]*cam0 + Km[4]*cam1 + Km[5]*cam2;
        const float pr2 = Km[6]*cam0 + Km[7]*cam1 + Km[8]*cam2;
        const float rz = 1.0f / pr2;
        const float mx = pr0 * rz;
        const float my = pr1 * rz;

        const float z   = cam2;
        const float iz  = 1.0f / z;
        const float jx0 = fx * iz;
        const float jx2 = -fx * cam0 * iz * iz;
        const float jy1 = fy * iz;
        const float jy2 = -fy * cam1 * iz * iz;

        // P = J * R  (2x3)
        const float P00 = jx0*r00 + jx2*r20;
        const float P01 = jx0*r01 + jx2*r21;
        const float P02 = jx0*r02 + jx2*r22;
        const float P10 = jy1*r10 + jy2*r20;
        const float P11 = jy1*r11 + jy2*r21;
        const float P12 = jy1*r12 + jy2*r22;

        // symmetric C
        const float c00 = cov3d[9*g+0];
        const float c01 = cov3d[9*g+1];
        const float c02 = cov3d[9*g+2];
        const float c11 = cov3d[9*g+4];
        const float c12 = cov3d[9*g+5];
        const float c22 = cov3d[9*g+8];

        const float t00 = c00*P00 + c01*P01 + c02*P02;
        const float t01 = c01*P00 + c11*P01 + c12*P02;
        const float t02 = c02*P00 + c12*P01 + c22*P02;
        const float t10 = c00*P10 + c01*P11 + c02*P12;
        const float t11 = c01*P10 + c11*P11 + c12*P12;
        const float t12 = c02*P10 + c12*P11 + c22*P12;

        const float a = P00*t00 + P01*t01 + P02*t02 + 0.3f;
        const float b = P10*t00 + P11*t01 + P12*t02;
        const float c = P10*t10 + P11*t11 + P12*t12 + 0.3f;

        const float det  = fmaxf(a*c - b*b, 1e-8f);
        const float idet = 1.0f / det;
        // exp2 prescale: exp(-0.5*m) = exp2(-0.72134752*m)
        const float e00 = -0.72134752f * c * idet;
        const float e01 =  1.44269504f * b * idet;
        const float e11 = -0.72134752f * a * idet;

        const float hd = (a - c) * 0.5f;
        const float max_eig = (a + c)*0.5f + sqrtf(fmaxf(hd*hd + b*b, 1e-8f));
        const float radius = 3.0f * sqrtf(max_eig);

        const float x_min = fmaxf(0.0f,       truncf(mx - radius));
        const float x_max = fminf((float)IMG, truncf(mx + radius) + 1.0f);
        const float y_min = fmaxf(0.0f,       truncf(my - radius));
        const float y_max = fminf((float)IMG, truncf(my + radius) + 1.0f);

        const float bias = __log2f(opac[g]);

        // u16-packed cull/mask words; empty boxes canonicalized to never-hit
        unsigned lo, hm1;
        if (x_max <= x_min || y_max <= y_min) {
            lo  = 0x7FFF7FFFu;
            hm1 = 0u;
        } else {
            lo  = (unsigned)x_min | ((unsigned)y_min << 16);
            hm1 = (unsigned)(x_max - 1.0f) | ((unsigned)(y_max - 1.0f) << 16);
        }

        const int x0  = (int)(lo & 0xffffu), y0  = (int)(lo >> 16);
        const int x1m = (int)(hm1 & 0xffffu), y1m = (int)(hm1 >> 16);
        flg[s] = (x0 < tileX + TW) & (x1m >= tileX) &
                 (y0 < tileY + TH) & (y1m >= tileY);
        key[s] = ((unsigned long long)__float_as_uint(z) << 16)
               | (unsigned long long)g;

        R0v[s] = make_float4(mx, my, e00, e01);
        R1v[s] = make_float4(e11, bias,
                             __uint_as_float(lo), __uint_as_float(hm1));
        R2v[s] = make_float4(cols[3*g+0], cols[3*g+1], cols[3*g+2], 0.f);
    }

    // ---------------- phase 2: compaction slots ----------------
    const unsigned m0 = __ballot_sync(0xffffffffu, flg[0]);
    const unsigned m1 = __ballot_sync(0xffffffffu, flg[1]);
    if (lane == 0) warpTotals[wid] = __popc(m0) | (__popc(m1) << 16);
    __syncthreads();

    int prefix = 0, total = 0;
    #pragma unroll
    for (int w = 0; w < NWARP; w++) {
        const int t = warpTotals[w];
        if (w < wid) prefix += t;
        total += t;
    }
    const int count0 = total & 0xffff;
    const int count  = count0 + (total >> 16);
    const unsigned lm = (1u << lane) - 1u;
    const int pos0 = (prefix & 0xffff) + __popc(m0 & lm);
    const int pos1 = count0 + (prefix >> 16) + __popc(m1 & lm);

    if (flg[0]) skey[pos0] = key[0];
    if (flg[1]) skey[pos1] = key[1];
    __syncthreads();

    // ---------------- phase 3: slot-parallel rank ----------------
    // Only ceil(count/32) warps run the O(count) loop.
    if (tid < count) {
        const unsigned long long k = skey[tid];
        int r = 0;
        for (int j = 0; j < count; j++)
            r += (skey[j] < k);
        srank[tid] = (short)r;
    }
    __syncthreads();

    // ---------------- phase 3b: owners scatter into depth order ----------
    if (flg[0]) {
        const int r = srank[pos0];
        rec[r][0] = R0v[0]; rec[r][1] = R1v[0]; rec[r][2] = R2v[0];
    }
    if (flg[1]) {
        const int r = srank[pos1];
        rec[r][0] = R0v[1]; rec[r][1] = R1v[1]; rec[r][2] = R2v[1];
    }
    const int countPad = (count + 3) & ~3;
    for (int t2 = count + tid; t2 < countPad; t2 += NT) {
        rec[t2][0] = make_float4(0.f, 0.f, 0.f, 0.f);
        rec[t2][1] = make_float4(0.f, 0.f,
                                 __uint_as_float(0x7FFF7FFFu), 0.f);
        rec[t2][2] = make_float4(0.f, 0.f, 0.f, 0.f);
    }
    __syncthreads();

    // ---------------- phase 4: composite, 1 px/thread ----------------
    const int pxi = tileX + (tid & (TW - 1));
    const int pyi = tileY + (tid >> 4);
    const float pxf = (float)pxi;
    const float pyf = (float)pyi;
    const unsigned pxy = (unsigned)pxi | ((unsigned)pyi << 16);

    float T = 1.0f, rr = 0.0f, gg = 0.0f, bb = 0.0f;
    for (int base = 0; base < countPad; base += 4) {
        float4 q0[4], q1[4], q2[4];
        #pragma unroll
        for (int i = 0; i < 4; i++) {
            q0[i] = rec[base+i][0];
            q1[i] = rec[base+i][1];
            q2[i] = rec[base+i][2];
        }
        float gs[4];
        #pragma unroll
        for (int i = 0; i < 4; i++) {
            const unsigned lo  = __float_as_uint(q1[i].z);
            const unsigned hm1 = __float_as_uint(q1[i].w);
            const unsigned ua  = __vsub2(pxy, lo);
            const unsigned ub  = __vsub2(hm1, pxy);
            const bool inb = ((ua | ub) & 0x80008000u) == 0u;

            const float dx = pxf - q0[i].x;
            const float dy = pyf - q0[i].y;
            const float u  = fmaf(q1[i].x * dy, dy, q1[i].y);   // e11*dy^2 + bias
            const float pl = fmaf(q0[i].w, dy, q0[i].z * dx);   // e01*dy + e00*dx
            const float e  = fmaf(pl, dx, u);
            gs[i] = inb ? ex2(e) : 0.0f;                        // alpha
        }
        #pragma unroll
        for (int i = 0; i < 4; i++) {
            const float tg = T * gs[i];
            rr = fmaf(tg, q2[i].x, rr);
            gg = fmaf(tg, q2[i].y, gg);
            bb = fmaf(tg, q2[i].z, bb);
            T  = T - tg;
        }
        if (T < 1e-5f) break;
    }

    const int idx = (pyi * IMG + pxi) * 3;
    out[idx + 0] = rr;
    out[idx + 1] = gg;
    out[idx + 2] = bb;
}

extern "C" void kernel_launch(void* const* d_in, const int* in_sizes, int n_in,
                              void* d_out, int out_size)
{
    const float* pos   = (const float*)d_in[0];  // (512,3)
    const float* cov3d = (const float*)d_in[1];  // (512,3,3)
    const float* opac  = (const float*)d_in[2];  // (512,1)
    const float* cols  = (const float*)d_in[3];  // (512,3)
    const float* Km    = (const float*)d_in[4];  // (3,3)
    const float* Rm    = (const float*)d_in[5];  // (3,3)
    const float* tv    = (const float*)d_in[6];  // (3,)
    float* out = (float*)d_out;                  // (256,256,3)

    gs_fused<<<dim3(IMG/TW, IMG/TH), NT>>>(pos, cov3d, opac, cols, Km, Rm, tv, out);
}

// round 15
// speedup vs baseline: 1.2156x; 1.0030x over previous
#include <cuda_runtime.h>
#include <cuda_bf16.h>
#include <cstdint>

// ---------------------------------------------------------------------------
// Fused Gaussian rasterizer, R15 = R14 pipeline, but 128 CTAs x 256 threads,
// each CTA projects once (registers) and rasterizes TWO paired 16x16 tiles:
//   tile0 = (tx, ty)  [ty in 0..7],  tile1 = ((tx+8)&15, ty+8)
// Half-period pairing anti-correlates tile load (center <-> corner).
// Single wave, projection amortized across both tiles.
// ---------------------------------------------------------------------------

#define NG    512
#define IMG   256
#define TW    16
#define TH    16
#define NT    256
#define NWARP (NT/32)

__device__ __forceinline__ float ex2(float x) {
    float y;
    asm("ex2.approx.ftz.f32 %0, %1;" : "=f"(y) : "f"(x));
    return y;
}

__global__ __launch_bounds__(NT)
void gs_fused(const float* __restrict__ pos,
              const float* __restrict__ cov3d,
              const float* __restrict__ opac,
              const float* __restrict__ cols,
              const float* __restrict__ Km,
              const float* __restrict__ Rm,
              const float* __restrict__ tv,
              float* __restrict__ out)
{
    __shared__ float4             rec[NG + 4][3];  // ~24.2 KB
    __shared__ unsigned long long skey[NG];        // 4 KB
    __shared__ short              srank[NG];       // 1 KB
    __shared__ int                warpTotals[NWARP];

    const int tid  = threadIdx.x;
    const int lane = tid & 31;
    const int wid  = tid >> 5;

    const int tx0 = blockIdx.x & 15;        // 0..15
    const int ty0 = blockIdx.x >> 4;        // 0..7

    const float r00 = Rm[0], r01 = Rm[1], r02 = Rm[2];
    const float r10 = Rm[3], r11 = Rm[4], r12 = Rm[5];
    const float r20 = Rm[6], r21 = Rm[7], r22 = Rm[8];
    const float fx  = Km[0], fy = Km[4];

    // ---------------- phase 1: project 2 gaussians/thread (once) ---------
    unsigned long long key[2];
    unsigned Flo[2], Fhm1[2];
    float4 R0v[2], R1v[2], R2v[2];

    #pragma unroll
    for (int s = 0; s < 2; s++) {
        const int g = tid + s * NT;
        const float p0 = pos[3*g+0], p1 = pos[3*g+1], p2 = pos[3*g+2];

        const float cam0 = r00*p0 + r01*p1 + r02*p2 + tv[0];
        const float cam1 = r10*p0 + r11*p1 + r12*p2 + tv[1];
        const float cam2 = r20*p0 + r21*p1 + r22*p2 + tv[2];

        const float pr0 = Km[0]*cam0 + Km[1]*cam1 + Km[2]*cam2;
        const float pr1 = Km[3]*cam0 + Km[4]*cam1 + Km[5]*cam2;
        const float pr2 = Km[6]*cam0 + Km[7]*cam1 + Km[8]*cam2;
        const float rz = 1.0f / pr2;
        const float mx = pr0 * rz;
        const float my = pr1 * rz;

        const float z   = cam2;
        const float iz  = 1.0f / z;
        const float jx0 = fx * iz;
        const float jx2 = -fx * cam0 * iz * iz;
        const float jy1 = fy * iz;
        const float jy2 = -fy * cam1 * iz * iz;

        // P = J * R  (2x3)
        const float P00 = jx0*r00 + jx2*r20;
        const float P01 = jx0*r01 + jx2*r21;
        const float P02 = jx0*r02 + jx2*r22;
        const float P10 = jy1*r10 + jy2*r20;
        const float P11 = jy1*r11 + jy2*r21;
        const float P12 = jy1*r12 + jy2*r22;

        // symmetric C
        const float c00 = cov3d[9*g+0];
        const float c01 = cov3d[9*g+1];
        const float c02 = cov3d[9*g+2];
        const float c11 = cov3d[9*g+4];
        const float c12 = cov3d[9*g+5];
        const float c22 = cov3d[9*g+8];

        const float t00 = c00*P00 + c01*P01 + c02*P02;
        const float t01 = c01*P00 + c11*P01 + c12*P02;
        const float t02 = c02*P00 + c12*P01 + c22*P02;
        const float t10 = c00*P10 + c01*P11 + c02*P12;
        const float t11 = c01*P10 + c11*P11 + c12*P12;
        const float t12 = c02*P10 + c12*P11 + c22*P12;

        const float a = P00*t00 + P01*t01 + P02*t02 + 0.3f;
        const float b = P10*t00 + P11*t01 + P12*t02;
        const float c = P10*t10 + P11*t11 + P12*t12 + 0.3f;

        const float det  = fmaxf(a*c - b*b, 1e-8f);
        const float idet = 1.0f / det;
        // exp2 prescale: exp(-0.5*m) = exp2(-0.72134752*m)
        const float e00 = -0.72134752f * c * idet;
        const float e01 =  1.44269504f * b * idet;
        const float e11 = -0.72134752f * a * idet;

        const float hd = (a - c) * 0.5f;
        const float max_eig = (a + c)*0.5f + sqrtf(fmaxf(hd*hd + b*b, 1e-8f));
        const float radius = 3.0f * sqrtf(max_eig);

        const float x_min = fmaxf(0.0f,       truncf(mx - radius));
        const float x_max = fminf((float)IMG, truncf(mx + radius) + 1.0f);
        const float y_min = fmaxf(0.0f,       truncf(my - radius));
        const float y_max = fminf((float)IMG, truncf(my + radius) + 1.0f);

        const float bias = __log2f(opac[g]);

        // u16-packed cull/mask words; empty boxes canonicalized to never-hit
        unsigned lo, hm1;
        if (x_max <= x_min || y_max <= y_min) {
            lo  = 0x7FFF7FFFu;
            hm1 = 0u;
        } else {
            lo  = (unsigned)x_min | ((unsigned)y_min << 16);
            hm1 = (unsigned)(x_max - 1.0f) | ((unsigned)(y_max - 1.0f) << 16);
        }
        Flo[s]  = lo;
        Fhm1[s] = hm1;

        key[s] = ((unsigned long long)__float_as_uint(z) << 16)
               | (unsigned long long)g;

        R0v[s] = make_float4(mx, my, e00, e01);
        R1v[s] = make_float4(e11, bias,
                             __uint_as_float(lo), __uint_as_float(hm1));
        R2v[s] = make_float4(cols[3*g+0], cols[3*g+1], cols[3*g+2], 0.f);
    }

    // =================== two paired tiles per CTA =======================
    #pragma unroll 1
    for (int tsel = 0; tsel < 2; tsel++) {
        const int tX = (tsel ? ((tx0 + 8) & 15) : tx0) * TW;
        const int tY = (tsel ? (ty0 + 8)        : ty0) * TH;

        // ---------------- phase 2: cull + compaction slots ----------------
        bool flg[2];
        #pragma unroll
        for (int s = 0; s < 2; s++) {
            const int x0  = (int)(Flo[s]  & 0xffffu), y0  = (int)(Flo[s]  >> 16);
            const int x1m = (int)(Fhm1[s] & 0xffffu), y1m = (int)(Fhm1[s] >> 16);
            flg[s] = (x0 < tX + TW) & (x1m >= tX) &
                     (y0 < tY + TH) & (y1m >= tY);
        }

        const unsigned m0 = __ballot_sync(0xffffffffu, flg[0]);
        const unsigned m1 = __ballot_sync(0xffffffffu, flg[1]);
        if (lane == 0) warpTotals[wid] = __popc(m0) | (__popc(m1) << 16);
        __syncthreads();

        int prefix = 0, total = 0;
        #pragma unroll
        for (int w = 0; w < NWARP; w++) {
            const int t = warpTotals[w];
            if (w < wid) prefix += t;
            total += t;
        }
        const int count0 = total & 0xffff;
        const int count  = count0 + (total >> 16);
        const unsigned lm = (1u << lane) - 1u;
        const int pos0 = (prefix & 0xffff) + __popc(m0 & lm);
        const int pos1 = count0 + (prefix >> 16) + __popc(m1 & lm);

        if (flg[0]) skey[pos0] = key[0];
        if (flg[1]) skey[pos1] = key[1];
        __syncthreads();

        // ---------------- phase 3: slot-parallel rank ----------------
        if (tid < count) {
            const unsigned long long k = skey[tid];
            int r = 0;
            for (int j = 0; j < count; j++)
                r += (skey[j] < k);
            srank[tid] = (short)r;
        }
        __syncthreads();

        // ---------------- phase 3b: owners scatter into depth order ------
        if (flg[0]) {
            const int r = srank[pos0];
            rec[r][0] = R0v[0]; rec[r][1] = R1v[0]; rec[r][2] = R2v[0];
        }
        if (flg[1]) {
            const int r = srank[pos1];
            rec[r][0] = R0v[1]; rec[r][1] = R1v[1]; rec[r][2] = R2v[1];
        }
        const int countPad = (count + 3) & ~3;
        for (int t2 = count + tid; t2 < countPad; t2 += NT) {
            rec[t2][0] = make_float4(0.f, 0.f, 0.f, 0.f);
            rec[t2][1] = make_float4(0.f, 0.f,
                                     __uint_as_float(0x7FFF7FFFu), 0.f);
            rec[t2][2] = make_float4(0.f, 0.f, 0.f, 0.f);
        }
        __syncthreads();

        // ---------------- phase 4: composite, 1 px/thread ----------------
        const int pxi = tX + (tid & (TW - 1));
        const int pyi = tY + (tid >> 4);
        const float pxf = (float)pxi;
        const float pyf = (float)pyi;
        const unsigned pxy = (unsigned)pxi | ((unsigned)pyi << 16);

        float T = 1.0f, rr = 0.0f, gg = 0.0f, bb = 0.0f;
        for (int base = 0; base < countPad; base += 4) {
            float4 q0[4], q1[4], q2[4];
            #pragma unroll
            for (int i = 0; i < 4; i++) {
                q0[i] = rec[base+i][0];
                q1[i] = rec[base+i][1];
                q2[i] = rec[base+i][2];
            }
            float gs[4];
            #pragma unroll
            for (int i = 0; i < 4; i++) {
                const unsigned lo  = __float_as_uint(q1[i].z);
                const unsigned hm1 = __float_as_uint(q1[i].w);
                const unsigned ua  = __vsub2(pxy, lo);
                const unsigned ub  = __vsub2(hm1, pxy);
                const bool inb = ((ua | ub) & 0x80008000u) == 0u;

                const float dx = pxf - q0[i].x;
                const float dy = pyf - q0[i].y;
                const float u  = fmaf(q1[i].x * dy, dy, q1[i].y); // e11*dy^2+bias
                const float pl = fmaf(q0[i].w, dy, q0[i].z * dx); // e01*dy+e00*dx
                const float e  = fmaf(pl, dx, u);
                gs[i] = inb ? ex2(e) : 0.0f;                      // alpha
            }
            #pragma unroll
            for (int i = 0; i < 4; i++) {
                const float tg = T * gs[i];
                rr = fmaf(tg, q2[i].x, rr);
                gg = fmaf(tg, q2[i].y, gg);
                bb = fmaf(tg, q2[i].z, bb);
                T  = T - tg;
            }
            if (T < 1e-5f) break;
        }

        const int idx = (pyi * IMG + pxi) * 3;
        out[idx + 0] = rr;
        out[idx + 1] = gg;
        out[idx + 2] = bb;

        __syncthreads();   // trec/skey reuse safety before next tile
    }
}

extern "C" void kernel_launch(void* const* d_in, const int* in_sizes, int n_in,
                              void* d_out, int out_size)
{
    const float* pos   = (const float*)d_in[0];  // (512,3)
    const float* cov3d = (const float*)d_in[1];  // (512,3,3)
    const float* opac  = (const float*)d_in[2];  // (512,1)
    const float* cols  = (const float*)d_in[3];  // (512,3)
    const float* Km    = (const float*)d_in[4];  // (3,3)
    const float* Rm    = (const float*)d_in[5];  // (3,3)
    const float* tv    = (const float*)d_in[6];  // (3,)
    float* out = (float*)d_out;                  // (256,256,3)

    gs_fused<<<128, NT>>>(pos, cov3d, opac, cols, Km, Rm, tv, out);
}